// round 5
// baseline (speedup 1.0000x reference)
#include <cuda_runtime.h>
#include <cuda_bf16.h>

// GraphSAGE 3-layer, mean aggregator, N=100000, E=1600000, F=64.
// R4 (= R3 resubmit; prior bench was an infra failure): fused per-layer kernel
// (aggregate -> smem -> transform), removing the g_agg global round-trip and
// overlapping gather-bound and FFMA-bound phases across blocks.
// Static init guard removed (harness determinism rule).

#define F 64
#define NMAX 100000
#define EMAX 1600000
#define SCAN_BS 512
#define NB 128           // nodes per fused block
#define NBPAD 129        // smem row pad (conflict-free phase-2 reads)

__device__ int   g_counts[NMAX];
__device__ int   g_cursor[NMAX];
__device__ int   g_row_off[NMAX + 1];
__device__ int   g_partials[256];
__device__ int   g_poff[256];
__device__ int   g_total;
__device__ int   g_csr[EMAX];
__device__ __align__(16) float g_bufA[(size_t)NMAX * F];
__device__ __align__(16) float g_bufB[(size_t)NMAX * F];

// ---------------------------------------------------------------- CSR build

__global__ void k_hist(const int* __restrict__ dst, int e) {
    int i = blockIdx.x * blockDim.x + threadIdx.x;
    if (i < e) atomicAdd(&g_counts[dst[i]], 1);
}

__global__ void k_scan_blocks(int n) {
    int i = blockIdx.x * SCAN_BS + threadIdx.x;
    int v = (i < n) ? g_counts[i] : 0;
    int lane = threadIdx.x & 31, wid = threadIdx.x >> 5;

    int incl = v;
    #pragma unroll
    for (int o = 1; o < 32; o <<= 1) {
        int x = __shfl_up_sync(0xffffffffu, incl, o);
        if (lane >= o) incl += x;
    }
    __shared__ int ws[16];
    if (lane == 31) ws[wid] = incl;
    __syncthreads();
    if (wid == 0) {
        int s = (lane < 16) ? ws[lane] : 0;
        #pragma unroll
        for (int o = 1; o < 16; o <<= 1) {
            int x = __shfl_up_sync(0xffffffffu, s, o);
            if (lane >= o) s += x;
        }
        if (lane < 16) ws[lane] = s;
    }
    __syncthreads();
    int excl = incl - v + (wid ? ws[wid - 1] : 0);
    if (i < n) g_cursor[i] = excl;
    if (threadIdx.x == SCAN_BS - 1) g_partials[blockIdx.x] = ws[15];
}

__global__ void k_scan_partials(int nb) {
    int t = threadIdx.x;
    int lane = t & 31, wid = t >> 5;
    int v = (t < nb) ? g_partials[t] : 0;
    int incl = v;
    #pragma unroll
    for (int o = 1; o < 32; o <<= 1) {
        int x = __shfl_up_sync(0xffffffffu, incl, o);
        if (lane >= o) incl += x;
    }
    __shared__ int ws[8];
    if (lane == 31) ws[wid] = incl;
    __syncthreads();
    if (wid == 0) {
        int s = (lane < 8) ? ws[lane] : 0;
        #pragma unroll
        for (int o = 1; o < 8; o <<= 1) {
            int x = __shfl_up_sync(0xffffffffu, s, o);
            if (lane >= o) s += x;
        }
        if (lane < 8) ws[lane] = s;
    }
    __syncthreads();
    incl += (wid ? ws[wid - 1] : 0);
    g_poff[t] = incl - v;
    if (t == 255) g_total = incl;
}

__global__ void k_scan_finalize(int n) {
    int i = blockIdx.x * SCAN_BS + threadIdx.x;
    if (i < n) {
        int off = g_cursor[i] + g_poff[i >> 9];
        g_row_off[i] = off;
        g_cursor[i]  = off;
        if (i == n - 1) g_row_off[n] = g_total;
    }
}

__global__ void k_scatter(const int* __restrict__ src, const int* __restrict__ dst, int e) {
    int i = blockIdx.x * blockDim.x + threadIdx.x;
    if (i < e) {
        int p = atomicAdd(&g_cursor[dst[i]], 1);
        g_csr[p] = src[i];
    }
}

// ---------------------------------------------------------------- fused layer

// Packed dual-FMA helpers (Blackwell f32x2 pipe)
__device__ __forceinline__ void ffma2(unsigned long long& acc,
                                      unsigned long long a,
                                      unsigned long long b) {
    asm("fma.rn.f32x2 %0, %1, %2, %0;" : "+l"(acc) : "l"(a), "l"(b));
}
__device__ __forceinline__ unsigned long long pack2(float h) {
    unsigned long long r;
    asm("mov.b64 %0, {%1, %1};" : "=l"(r) : "f"(h));
    return r;
}
__device__ __forceinline__ void unpack2(unsigned long long p, float& lo, float& hi) {
    asm("mov.b64 {%0, %1}, %2;" : "=f"(lo), "=f"(hi) : "l"(p));
}

// acc pairs += hk * Wt[k][:], for 4 consecutive k values
__device__ __forceinline__ void mac4(const float hk[4], const float* __restrict__ Wt,
                                     int k0, unsigned long long acc[F / 2]) {
    #pragma unroll
    for (int kk = 0; kk < 4; kk++) {
        unsigned long long hh = pack2(hk[kk]);
        const ulonglong2* wr = (const ulonglong2*)&Wt[(k0 + kk) * F];
        #pragma unroll
        for (int j = 0; j < 16; j++) {
            ulonglong2 w = wr[j];
            ffma2(acc[2 * j + 0], hh, w.x);
            ffma2(acc[2 * j + 1], hh, w.y);
        }
    }
}

__global__ void k_layer(const float* __restrict__ h,
                        const float* __restrict__ Ws,
                        const float* __restrict__ Wn,
                        const float* __restrict__ b,
                        float* __restrict__ out,
                        int n, int leaky) {
    extern __shared__ float smem[];
    float* sT  = smem;                  // [F][NBPAD] transposed agg tile
    float* Wts = smem + F * NBPAD;      // [F][F] W_self^T
    float* Wtn = Wts + F * F;           // [F][F] W_neigh^T
    float* sb  = Wtn + F * F;           // [F]

    int t = threadIdx.x;                // 0..127
    int lane = t & 31, w = t >> 5;

    for (int i = t; i < F * F; i += NB) {
        int j = i >> 6, k = i & 63;     // W[j][k] -> Wt[k][j]
        Wts[k * F + j] = Ws[i];
        Wtn[k * F + j] = Wn[i];
    }
    if (t < F) sb[t] = b[t];

    // ---- phase 1: warp w aggregates local nodes [w*32, (w+1)*32) ----
    int base = blockIdx.x * NB;
    const float2* hp = (const float2*)h;
    for (int it = 0; it < 32; it++) {
        int local = w * 32 + it;
        int node = base + local;
        if (node >= n) break;
        int beg = g_row_off[node];
        int end = g_row_off[node + 1];
        float ax = 0.f, ay = 0.f;
        int e = beg;
        for (; e + 4 <= end; e += 4) {
            int s0 = g_csr[e + 0];
            int s1 = g_csr[e + 1];
            int s2 = g_csr[e + 2];
            int s3 = g_csr[e + 3];
            float2 v0 = hp[(size_t)s0 * 32 + lane];
            float2 v1 = hp[(size_t)s1 * 32 + lane];
            float2 v2 = hp[(size_t)s2 * 32 + lane];
            float2 v3 = hp[(size_t)s3 * 32 + lane];
            ax += (v0.x + v1.x) + (v2.x + v3.x);
            ay += (v0.y + v1.y) + (v2.y + v3.y);
        }
        for (; e < end; e++) {
            float2 v = hp[(size_t)g_csr[e] * 32 + lane];
            ax += v.x;
            ay += v.y;
        }
        int deg = end - beg;
        float inv = 1.f / (float)(deg > 0 ? deg : 1);
        sT[(2 * lane + 0) * NBPAD + local] = ax * inv;
        sT[(2 * lane + 1) * NBPAD + local] = ay * inv;
    }
    __syncthreads();

    // ---- phase 2: thread t transforms node base+t ----
    int node = base + t;
    if (node >= n) return;

    unsigned long long acc[F / 2];
    const unsigned long long* bp = (const unsigned long long*)sb;
    #pragma unroll
    for (int j = 0; j < F / 2; j++) acc[j] = bp[j];

    const float4* hrow = (const float4*)(h + (size_t)node * F);
    for (int k0 = 0; k0 < F; k0 += 4) {       // self term (global, L1/L2-resident)
        float4 hv = hrow[k0 >> 2];
        float hk[4] = {hv.x, hv.y, hv.z, hv.w};
        mac4(hk, Wts, k0, acc);
    }
    for (int k0 = 0; k0 < F; k0 += 4) {       // neighbor term (smem, transposed)
        float hk[4];
        #pragma unroll
        for (int kk = 0; kk < 4; kk++) hk[kk] = sT[(k0 + kk) * NBPAD + t];
        mac4(hk, Wtn, k0, acc);
    }

    float4* o = (float4*)(out + (size_t)node * F);
    #pragma unroll
    for (int j4 = 0; j4 < 16; j4++) {
        float a0, a1, a2, a3;
        unpack2(acc[2 * j4 + 0], a0, a1);
        unpack2(acc[2 * j4 + 1], a2, a3);
        float4 v;
        if (leaky) {
            v.x = a0 >= 0.f ? a0 : 0.01f * a0;
            v.y = a1 >= 0.f ? a1 : 0.01f * a1;
            v.z = a2 >= 0.f ? a2 : 0.01f * a2;
            v.w = a3 >= 0.f ? a3 : 0.01f * a3;
        } else {
            v.x = a0; v.y = a1; v.z = a2; v.w = a3;
        }
        o[j4] = v;
    }
}

// ---------------------------------------------------------------- launch

static const int SMEM_LAYER = (F * NBPAD + 2 * F * F + F) * (int)sizeof(float); // 66304

extern "C" void kernel_launch(void* const* d_in, const int* in_sizes, int n_in,
                              void* d_out, int out_size) {
    const float* in_feat = (const float*)d_in[0];
    const int*   src     = (const int*)d_in[1];
    const int*   dst     = (const int*)d_in[2];
    const float* w_self1 = (const float*)d_in[3];
    const float* w_nei1  = (const float*)d_in[4];
    const float* b1      = (const float*)d_in[5];
    const float* w_self2 = (const float*)d_in[6];
    const float* w_nei2  = (const float*)d_in[7];
    const float* b2      = (const float*)d_in[8];
    const float* w_self3 = (const float*)d_in[9];
    const float* w_nei3  = (const float*)d_in[10];
    const float* b3      = (const float*)d_in[11];
    float* out = (float*)d_out;

    int n = in_sizes[0] / F;     // 100000
    int e = in_sizes[1];         // 1600000
    int nscan = (n + SCAN_BS - 1) / SCAN_BS;

    float *bufA, *bufB;
    int* counts;
    cudaGetSymbolAddress((void**)&bufA, g_bufA);
    cudaGetSymbolAddress((void**)&bufB, g_bufB);
    cudaGetSymbolAddress((void**)&counts, g_counts);

    // idempotent, host-side, capture-safe; done unconditionally each call
    cudaFuncSetAttribute(k_layer, cudaFuncAttributeMaxDynamicSharedMemorySize,
                         SMEM_LAYER);

    // ---- CSR build (once per launch) ----
    cudaMemsetAsync(counts, 0, (size_t)n * sizeof(int));
    k_hist<<<(e + 255) / 256, 256>>>(dst, e);
    k_scan_blocks<<<nscan, SCAN_BS>>>(n);
    k_scan_partials<<<1, 256>>>(nscan);
    k_scan_finalize<<<nscan, SCAN_BS>>>(n);
    k_scatter<<<(e + 255) / 256, 256>>>(src, dst, e);

    int grid = (n + NB - 1) / NB;   // 782

    k_layer<<<grid, NB, SMEM_LAYER>>>(in_feat, w_self1, w_nei1, b1, bufA, n, 1);
    k_layer<<<grid, NB, SMEM_LAYER>>>(bufA,    w_self2, w_nei2, b2, bufB, n, 1);
    k_layer<<<grid, NB, SMEM_LAYER>>>(bufB,    w_self3, w_nei3, b3, out,  n, 0);
}

// round 6
// speedup vs baseline: 1.6233x; 1.6233x over previous
#include <cuda_runtime.h>
#include <cuda_fp16.h>
#include <cuda_bf16.h>

// GraphSAGE 3-layer, mean aggregator, N=100000, E=1600000, F=64.
// R6: revert to R2 split structure (fusion regressed: occupancy-starved gather).
//     New: fp16 shadow copy of h for the aggregate gather (halves the dominant
//     L2 gather traffic, 264 -> 136 B/edge); fp32 accumulation and fp32 self
//     term keep accuracy (~1e-4 expected vs 1e-3 threshold).

#define F 64
#define NMAX 100000
#define EMAX 1600000
#define SCAN_BS 512

__device__ int   g_counts[NMAX];
__device__ int   g_cursor[NMAX];
__device__ int   g_row_off[NMAX + 1];
__device__ int   g_partials[256];
__device__ int   g_poff[256];
__device__ int   g_total;
__device__ int   g_csr[EMAX];
__device__ __align__(16) float  g_bufA[(size_t)NMAX * F];
__device__ __align__(16) float  g_bufB[(size_t)NMAX * F];
__device__ __align__(16) float  g_agg [(size_t)NMAX * F];
__device__ __align__(16) __half g_h16 [(size_t)NMAX * F];

// ---------------------------------------------------------------- CSR build

__global__ void k_hist(const int* __restrict__ dst, int e) {
    int i = blockIdx.x * blockDim.x + threadIdx.x;
    if (i < e) atomicAdd(&g_counts[dst[i]], 1);
}

__global__ void k_scan_blocks(int n) {
    int i = blockIdx.x * SCAN_BS + threadIdx.x;
    int v = (i < n) ? g_counts[i] : 0;
    int lane = threadIdx.x & 31, wid = threadIdx.x >> 5;

    int incl = v;
    #pragma unroll
    for (int o = 1; o < 32; o <<= 1) {
        int x = __shfl_up_sync(0xffffffffu, incl, o);
        if (lane >= o) incl += x;
    }
    __shared__ int ws[16];
    if (lane == 31) ws[wid] = incl;
    __syncthreads();
    if (wid == 0) {
        int s = (lane < 16) ? ws[lane] : 0;
        #pragma unroll
        for (int o = 1; o < 16; o <<= 1) {
            int x = __shfl_up_sync(0xffffffffu, s, o);
            if (lane >= o) s += x;
        }
        if (lane < 16) ws[lane] = s;
    }
    __syncthreads();
    int excl = incl - v + (wid ? ws[wid - 1] : 0);
    if (i < n) g_cursor[i] = excl;
    if (threadIdx.x == SCAN_BS - 1) g_partials[blockIdx.x] = ws[15];
}

__global__ void k_scan_partials(int nb) {
    int t = threadIdx.x;
    int lane = t & 31, wid = t >> 5;
    int v = (t < nb) ? g_partials[t] : 0;
    int incl = v;
    #pragma unroll
    for (int o = 1; o < 32; o <<= 1) {
        int x = __shfl_up_sync(0xffffffffu, incl, o);
        if (lane >= o) incl += x;
    }
    __shared__ int ws[8];
    if (lane == 31) ws[wid] = incl;
    __syncthreads();
    if (wid == 0) {
        int s = (lane < 8) ? ws[lane] : 0;
        #pragma unroll
        for (int o = 1; o < 8; o <<= 1) {
            int x = __shfl_up_sync(0xffffffffu, s, o);
            if (lane >= o) s += x;
        }
        if (lane < 8) ws[lane] = s;
    }
    __syncthreads();
    incl += (wid ? ws[wid - 1] : 0);
    g_poff[t] = incl - v;
    if (t == 255) g_total = incl;
}

__global__ void k_scan_finalize(int n) {
    int i = blockIdx.x * SCAN_BS + threadIdx.x;
    if (i < n) {
        int off = g_cursor[i] + g_poff[i >> 9];
        g_row_off[i] = off;
        g_cursor[i]  = off;
        if (i == n - 1) g_row_off[n] = g_total;
    }
}

__global__ void k_scatter(const int* __restrict__ src, const int* __restrict__ dst, int e) {
    int i = blockIdx.x * blockDim.x + threadIdx.x;
    if (i < e) {
        int p = atomicAdd(&g_cursor[dst[i]], 1);
        g_csr[p] = src[i];
    }
}

// ---------------------------------------------------------------- fp16 shadow

__global__ void k_tofp16(const float* __restrict__ in, int n2) {
    int i = blockIdx.x * blockDim.x + threadIdx.x;   // over N*F/2 half2 slots
    if (i < n2) {
        float2 v = ((const float2*)in)[i];
        ((__half2*)g_h16)[i] = __float22half2_rn(v);
    }
}

// ---------------------------------------------------------------- aggregate

// One warp per node. Lane l owns features [2l, 2l+1]. Gather fp16, accum fp32.
__global__ void k_aggregate(int n) {
    int gtid = blockIdx.x * blockDim.x + threadIdx.x;
    int node = gtid >> 5;
    int lane = gtid & 31;
    if (node >= n) return;

    int beg = g_row_off[node];
    int end = g_row_off[node + 1];
    const __half2* hp = (const __half2*)g_h16;

    float ax = 0.f, ay = 0.f;
    int e = beg;
    for (; e + 4 <= end; e += 4) {
        int s0 = g_csr[e + 0];
        int s1 = g_csr[e + 1];
        int s2 = g_csr[e + 2];
        int s3 = g_csr[e + 3];
        float2 v0 = __half22float2(hp[(size_t)s0 * 32 + lane]);
        float2 v1 = __half22float2(hp[(size_t)s1 * 32 + lane]);
        float2 v2 = __half22float2(hp[(size_t)s2 * 32 + lane]);
        float2 v3 = __half22float2(hp[(size_t)s3 * 32 + lane]);
        ax += (v0.x + v1.x) + (v2.x + v3.x);
        ay += (v0.y + v1.y) + (v2.y + v3.y);
    }
    for (; e < end; e++) {
        float2 v = __half22float2(hp[(size_t)g_csr[e] * 32 + lane]);
        ax += v.x;
        ay += v.y;
    }
    int deg = end - beg;
    float inv = 1.f / (float)(deg > 0 ? deg : 1);
    float2 r;
    r.x = ax * inv;
    r.y = ay * inv;
    ((float2*)g_agg)[(size_t)node * 32 + lane] = r;
}

// ---------------------------------------------------------------- transform

// Packed dual-FMA helpers (Blackwell f32x2 pipe)
__device__ __forceinline__ void ffma2(unsigned long long& acc,
                                      unsigned long long a,
                                      unsigned long long b) {
    asm("fma.rn.f32x2 %0, %1, %2, %0;" : "+l"(acc) : "l"(a), "l"(b));
}
__device__ __forceinline__ unsigned long long pack2(float h) {
    unsigned long long r;
    asm("mov.b64 %0, {%1, %1};" : "=l"(r) : "f"(h));
    return r;
}
__device__ __forceinline__ void unpack2(unsigned long long p, float& lo, float& hi) {
    asm("mov.b64 {%0, %1}, %2;" : "=f"(lo), "=f"(hi) : "l"(p));
}

// acc[j] pair += row[k] * Wt[k][2j..2j+1], Wt transposed in smem (broadcast reads)
__device__ __forceinline__ void mac_row2(const float* __restrict__ row,
                                         const float* __restrict__ Wt,
                                         unsigned long long acc[F / 2]) {
    for (int k0 = 0; k0 < F; k0 += 4) {          // NOT unrolled (keep I$ small)
        float4 hv = ((const float4*)row)[k0 >> 2];
        float hk[4] = {hv.x, hv.y, hv.z, hv.w};
        #pragma unroll
        for (int kk = 0; kk < 4; kk++) {
            unsigned long long hh = pack2(hk[kk]);
            const ulonglong2* wr = (const ulonglong2*)&Wt[(k0 + kk) * F];
            #pragma unroll
            for (int j = 0; j < 16; j++) {
                ulonglong2 w = wr[j];
                ffma2(acc[2 * j + 0], hh, w.x);
                ffma2(acc[2 * j + 1], hh, w.y);
            }
        }
    }
}

// write16: also emit fp16 shadow of output into g_h16 (for next layer's gather)
__global__ void k_transform(const float* __restrict__ h,
                            const float* __restrict__ agg,
                            const float* __restrict__ Ws,
                            const float* __restrict__ Wn,
                            const float* __restrict__ b,
                            float* __restrict__ out,
                            int n, int leaky, int write16) {
    __shared__ __align__(16) float Wts[F * F];
    __shared__ __align__(16) float Wtn[F * F];
    __shared__ __align__(16) float sb[F];

    int t = threadIdx.x;
    for (int i = t; i < F * F; i += blockDim.x) {
        int j = i >> 6, k = i & 63;              // W[j][k] -> Wt[k][j]
        Wts[k * F + j] = Ws[i];
        Wtn[k * F + j] = Wn[i];
    }
    if (t < F) sb[t] = b[t];
    __syncthreads();

    int node = blockIdx.x * blockDim.x + t;
    if (node >= n) return;

    unsigned long long acc[F / 2];
    const unsigned long long* bp = (const unsigned long long*)sb;
    #pragma unroll
    for (int j = 0; j < F / 2; j++) acc[j] = bp[j];

    mac_row2(h   + (size_t)node * F, Wts, acc);
    mac_row2(agg + (size_t)node * F, Wtn, acc);

    float4*  o   = (float4*)(out + (size_t)node * F);
    __half2* o16 = ((__half2*)g_h16) + (size_t)node * 32;
    #pragma unroll
    for (int j4 = 0; j4 < 16; j4++) {
        float a0, a1, a2, a3;
        unpack2(acc[2 * j4 + 0], a0, a1);
        unpack2(acc[2 * j4 + 1], a2, a3);
        float4 v;
        if (leaky) {
            v.x = a0 >= 0.f ? a0 : 0.01f * a0;
            v.y = a1 >= 0.f ? a1 : 0.01f * a1;
            v.z = a2 >= 0.f ? a2 : 0.01f * a2;
            v.w = a3 >= 0.f ? a3 : 0.01f * a3;
        } else {
            v.x = a0; v.y = a1; v.z = a2; v.w = a3;
        }
        o[j4] = v;
        if (write16) {
            o16[2 * j4 + 0] = __float22half2_rn(make_float2(v.x, v.y));
            o16[2 * j4 + 1] = __float22half2_rn(make_float2(v.z, v.w));
        }
    }
}

// ---------------------------------------------------------------- launch

extern "C" void kernel_launch(void* const* d_in, const int* in_sizes, int n_in,
                              void* d_out, int out_size) {
    const float* in_feat = (const float*)d_in[0];
    const int*   src     = (const int*)d_in[1];
    const int*   dst     = (const int*)d_in[2];
    const float* w_self1 = (const float*)d_in[3];
    const float* w_nei1  = (const float*)d_in[4];
    const float* b1      = (const float*)d_in[5];
    const float* w_self2 = (const float*)d_in[6];
    const float* w_nei2  = (const float*)d_in[7];
    const float* b2      = (const float*)d_in[8];
    const float* w_self3 = (const float*)d_in[9];
    const float* w_nei3  = (const float*)d_in[10];
    const float* b3      = (const float*)d_in[11];
    float* out = (float*)d_out;

    int n = in_sizes[0] / F;     // 100000
    int e = in_sizes[1];         // 1600000
    int nscan = (n + SCAN_BS - 1) / SCAN_BS;

    float *bufA, *bufB, *agg;
    int* counts;
    cudaGetSymbolAddress((void**)&bufA, g_bufA);
    cudaGetSymbolAddress((void**)&bufB, g_bufB);
    cudaGetSymbolAddress((void**)&agg,  g_agg);
    cudaGetSymbolAddress((void**)&counts, g_counts);

    // ---- CSR build (once per launch) ----
    cudaMemsetAsync(counts, 0, (size_t)n * sizeof(int));
    k_hist<<<(e + 255) / 256, 256>>>(dst, e);
    k_scan_blocks<<<nscan, SCAN_BS>>>(n);
    k_scan_partials<<<1, 256>>>(nscan);
    k_scan_finalize<<<nscan, SCAN_BS>>>(n);
    k_scatter<<<(e + 255) / 256, 256>>>(src, dst, e);

    // fp16 shadow of the input features
    int n2 = n * F / 2;
    k_tofp16<<<(n2 + 255) / 256, 256>>>(in_feat, n2);

    int agg_grid = (n * 32 + 255) / 256;   // warp per node
    int tr_grid  = (n + 255) / 256;

    // ---- layer 1 ----
    k_aggregate<<<agg_grid, 256>>>(n);
    k_transform<<<tr_grid, 256>>>(in_feat, agg, w_self1, w_nei1, b1, bufA, n, 1, 1);
    // ---- layer 2 ----
    k_aggregate<<<agg_grid, 256>>>(n);
    k_transform<<<tr_grid, 256>>>(bufA, agg, w_self2, w_nei2, b2, bufB, n, 1, 1);
    // ---- layer 3 ----
    k_aggregate<<<agg_grid, 256>>>(n);
    k_transform<<<tr_grid, 256>>>(bufB, agg, w_self3, w_nei3, b3, out, n, 0, 0);
}